// round 17
// baseline (speedup 1.0000x reference)
#include <cuda_runtime.h>
#include <math.h>

// EntropyLoss: x [R=65536, C=1024] f32 row-major.
//   n_j  = max( sqrt(sum_i x_ij^2), 1e-12 )
//   out  = -(1/R) * sum_j (1/n_j) * [ sum_i x*ln(x) - ln(n_j) * sum_i x ]
// (eps=1e-8 inside the reference log contributes <1e-6 relative error; dropped)
//
// R17 = R16 (best: 47.52us, DRAM 75.6%) + packed f32x2 accumulation for sx
// as well: per float4 the 4 scalar FFMAs for sum x*log2(x) become 2
// fma.rn.f32x2 (R16 proved this mechanism: fewer issue slots in the body ->
// earlier dispatch of the 8-load front batch -> higher sustained DRAM%).
// s2/s1 already packed. MUFU LG2 and FMNMX stay scalar (no packed forms).
// Mainloop config: 5 CTAs/SM, 48-reg budget, fixed-8 front-batched float4
// loads, grid-strided rows, 4 column tiles; parallel per-tile tail.
// All scratch/counters re-zeroed each call for clean graph replays.

#define COLS 1024
#define GRID_X 185          // 185*4 = 740 CTAs = 5/SM, one wave
#define GRID_Y 4            // column tiles of 256
#define LN2 0.6931471805599453f

__device__ float g_part[3][COLS];      // [0]=sum x^2, [1]=sum x, [2]=sum x*log2(x)
__device__ float g_tile[GRID_Y];
__device__ unsigned int g_tile_count[GRID_Y];
__device__ unsigned int g_final;

__device__ __forceinline__ unsigned long long pack2(float lo, float hi) {
    unsigned long long r;
    asm("mov.b64 %0, {%1, %2};" : "=l"(r) : "f"(lo), "f"(hi));
    return r;
}
__device__ __forceinline__ void unpack2(unsigned long long v, float& lo, float& hi) {
    asm("mov.b64 {%0, %1}, %2;" : "=f"(lo), "=f"(hi) : "l"(v));
}
// acc += a*a (two f32 lanes)
__device__ __forceinline__ void fma2_sq(unsigned long long& acc, unsigned long long a) {
    asm("fma.rn.f32x2 %0, %1, %2, %0;" : "+l"(acc) : "l"(a), "l"(a));
}
// acc += a*b (two f32 lanes)
__device__ __forceinline__ void fma2_ab(unsigned long long& acc, unsigned long long a,
                                        unsigned long long b) {
    asm("fma.rn.f32x2 %0, %1, %2, %0;" : "+l"(acc) : "l"(a), "l"(b));
}
__device__ __forceinline__ void add2_acc(unsigned long long& acc, unsigned long long a) {
    asm("add.rn.f32x2 %0, %1, %0;" : "+l"(acc) : "l"(a));
}

__global__ __launch_bounds__(256, 5) void el_fused_kernel(const float* __restrict__ x,
                                                          float* __restrict__ out,
                                                          int rows) {
    const int tid     = threadIdx.x;
    const int cg      = tid & 63;     // 64 float4 column-groups per block (256 cols)
    const int slice   = tid >> 6;     // 4 row slices per block
    const int ty      = blockIdx.y;
    const int colbase = ty * 256;
    const int g4      = (colbase >> 2) + cg;   // float4 index within a row

    const float4* __restrict__ p = (const float4*)x;

    unsigned long long S2p[2] = {0ull, 0ull};  // packed sum x^2
    unsigned long long S1p[2] = {0ull, 0ull};  // packed sum x
    unsigned long long SXp[2] = {0ull, 0ull};  // packed sum x*log2(x)

    const int  rstride = GRID_X * 4;                 // 740 row slices total
    const int  r0      = blockIdx.x * 4 + slice;
    const long step    = (long)rstride * (COLS / 4);
    const float4* __restrict__ q = p + (long)r0 * (COLS / 4) + g4;

    const int iters = (rows - r0 + rstride - 1) / rstride;   // ~88-89
    const int it8   = iters & ~7;

    for (int b = 0; b < it8; b += 8) {
        // fixed trip count of 8: fully unrolled, 8 independent front-batched
        // float4 loads (the validated R6 shape)
        #pragma unroll
        for (int u = 0; u < 8; u++) {
            float4 v = q[(long)u * step];
            unsigned long long a01 = pack2(v.x, v.y);
            unsigned long long a23 = pack2(v.z, v.w);
            fma2_sq(S2p[0], a01);   fma2_sq(S2p[1], a23);
            add2_acc(S1p[0], a01);  add2_acc(S1p[1], a23);
            // x*log2(x): at a==0 the packed fma gets l finite (lg2 1e-37), so
            // lane contributes 0*l == 0 (correct limit)
            float l0 = __log2f(fmaxf(v.x, 1e-37f));
            float l1 = __log2f(fmaxf(v.y, 1e-37f));
            float l2 = __log2f(fmaxf(v.z, 1e-37f));
            float l3 = __log2f(fmaxf(v.w, 1e-37f));
            fma2_ab(SXp[0], a01, pack2(l0, l1));
            fma2_ab(SXp[1], a23, pack2(l2, l3));
        }
        q += 8 * step;
    }
    for (int i = it8; i < iters; i++) {
        float4 v = *q;
        q += step;
        unsigned long long a01 = pack2(v.x, v.y);
        unsigned long long a23 = pack2(v.z, v.w);
        fma2_sq(S2p[0], a01);   fma2_sq(S2p[1], a23);
        add2_acc(S1p[0], a01);  add2_acc(S1p[1], a23);
        float l0 = __log2f(fmaxf(v.x, 1e-37f));
        float l1 = __log2f(fmaxf(v.y, 1e-37f));
        float l2 = __log2f(fmaxf(v.z, 1e-37f));
        float l3 = __log2f(fmaxf(v.w, 1e-37f));
        fma2_ab(SXp[0], a01, pack2(l0, l1));
        fma2_ab(SXp[1], a23, pack2(l2, l3));
    }

    float s2[4], s1[4], sx[4];
    unpack2(S2p[0], s2[0], s2[1]);  unpack2(S2p[1], s2[2], s2[3]);
    unpack2(S1p[0], s1[0], s1[1]);  unpack2(S1p[1], s1[2], s1[3]);
    unpack2(SXp[0], sx[0], sx[1]);  unpack2(SXp[1], sx[2], sx[3]);

    // Reduce the 4 row-slices within the block before touching L2 atomics.
    __shared__ float red[4][64 * 12];
    #pragma unroll
    for (int k = 0; k < 4; k++) {
        red[slice][cg * 12 + 0 + k] = s2[k];
        red[slice][cg * 12 + 4 + k] = s1[k];
        red[slice][cg * 12 + 8 + k] = sx[k];
    }
    __syncthreads();

    for (int i = tid; i < 64 * 12; i += 256) {
        float t = red[0][i] + red[1][i] + red[2][i] + red[3][i];
        int cg2  = i / 12;
        int comp = i % 12;
        int type = comp >> 2;     // 0: x^2, 1: x, 2: x*log2(x)
        int sub  = comp & 3;
        int col  = colbase + cg2 * 4 + sub;
        atomicAdd(&g_part[type][col], t);
    }

    // ---- per-tile last block: combine this tile's 256 columns ----
    __shared__ int amTileLast;
    __threadfence();
    __syncthreads();
    if (tid == 0) {
        unsigned v = atomicAdd(&g_tile_count[ty], 1u);
        amTileLast = (v == GRID_X - 1);
    }
    __syncthreads();
    if (!amTileLast) return;

    {
        const int j = colbase + tid;   // each thread owns one column of the tile
        float S2 = __ldcg(&g_part[0][j]);
        float S1 = __ldcg(&g_part[1][j]);
        float SX = __ldcg(&g_part[2][j]);
        float n  = fmaxf(sqrtf(S2), 1e-12f);
        float t  = (SX * LN2 - S1 * logf(n)) / n;

        // re-zero this tile's scratch for the next graph replay
        g_part[0][j] = 0.0f;
        g_part[1][j] = 0.0f;
        g_part[2][j] = 0.0f;
        if (tid == 0) g_tile_count[ty] = 0u;

        __shared__ float sm[256];
        sm[tid] = t;
        __syncthreads();
        #pragma unroll
        for (int s = 128; s > 0; s >>= 1) {
            if (tid < s) sm[tid] += sm[tid + s];
            __syncthreads();
        }
        if (tid == 0) g_tile[ty] = sm[0];
    }

    // ---- global last tile writes the output ----
    __shared__ int amFinal;
    __threadfence();
    __syncthreads();
    if (tid == 0) {
        unsigned v = atomicAdd(&g_final, 1u);
        amFinal = (v == GRID_Y - 1);
    }
    __syncthreads();
    if (!amFinal) return;

    if (tid == 0) {
        float s = 0.f;
        #pragma unroll
        for (int m = 0; m < GRID_Y; m++) s += __ldcg(&g_tile[m]);
        out[0] = -s / (float)rows;
        g_final = 0u;
    }
}

extern "C" void kernel_launch(void* const* d_in, const int* in_sizes, int n_in,
                              void* d_out, int out_size) {
    const float* x = (const float*)d_in[0];
    int rows = in_sizes[0] / COLS;   // 65536
    dim3 grid(GRID_X, GRID_Y);
    el_fused_kernel<<<grid, 256>>>(x, (float*)d_out, rows);
}